// round 12
// baseline (speedup 1.0000x reference)
#include <cuda_runtime.h>

// ADC module: out = x + alpha_c * sum_{3x3, zero-pad} |x - neighbor|
// x: (8, 64, 256, 256) fp32, alpha: (64,) fp32
//
// R10: smem-staged tile (R7 design, warp-count bug fixed).
// One 256-thread block (8 warps) per 32-row strip. Phase 1 bulk-copies the
// 34-row tile (strip + halos) into smem: 9 independent LDG.128 per thread,
// high MLP, no register rotation. Phase 2: warp w computes output rows
// r0+4w .. r0+4w+3 from a 3-row rolling window over smem rows 4w..4w+5
// (conflict-free LDS.128 + shfl lane halos).
// 35.9KB smem -> 6 blocks/SM; phase-offset blocks overlap load and compute.

#define IMG_H 256
#define IMG_W 256
#define STRIP_ROWS 32
#define N_IMG (8 * 64)
#define STRIPS_PER_IMG (IMG_H / STRIP_ROWS)        // 8
#define GRID_BLOCKS (N_IMG * STRIPS_PER_IMG)       // 4096
#define BLOCK_THREADS 256
#define ROWS_PER_WARP 4                             // 8 warps * 4 = 32 rows

#define TILE_ROWS (STRIP_ROWS + 2)                 // 34
#define ROW_F4 (IMG_W / 4)                         // 64 float4 per row
#define PAD_F4 66                                  // padded row stride in float4
#define TILE_F4 (TILE_ROWS * ROW_F4)               // 2176 float4 loads

struct Row {
    float v[8];
    float lh, rh;
};

__device__ __forceinline__ Row load_srow(const float4* __restrict__ tile,
                                         int i, int lane) {
    Row row;
    const float4* sr = tile + i * PAD_F4 + lane * 2;
    float4 va = sr[0];
    float4 vb = sr[1];
    row.v[0] = va.x; row.v[1] = va.y; row.v[2] = va.z; row.v[3] = va.w;
    row.v[4] = vb.x; row.v[5] = vb.y; row.v[6] = vb.z; row.v[7] = vb.w;
    float left  = __shfl_up_sync(0xffffffffu, row.v[7], 1);
    float right = __shfl_down_sync(0xffffffffu, row.v[0], 1);
    row.lh = (lane == 0)  ? 0.0f : left;
    row.rh = (lane == 31) ? 0.0f : right;
    return row;
}

__device__ __forceinline__ void compute_store(const Row& p, const Row& c, const Row& n,
                                              float a, float4* __restrict__ oi,
                                              int r, int lane) {
    float o[8];
#pragma unroll
    for (int j = 0; j < 8; ++j) {
        float cc = c.v[j];
        float pl = (j == 0) ? p.lh : p.v[j - 1];
        float pc = p.v[j];
        float pr = (j == 7) ? p.rh : p.v[j + 1];
        float l  = (j == 0) ? c.lh : c.v[j - 1];
        float rr = (j == 7) ? c.rh : c.v[j + 1];
        float nl = (j == 0) ? n.lh : n.v[j - 1];
        float nc = n.v[j];
        float nr = (j == 7) ? n.rh : n.v[j + 1];

        // center tap |c-c| == 0 for finite inputs -> skipped
        float s = fabsf(cc - pl) + fabsf(cc - pc) + fabsf(cc - pr)
                + fabsf(cc - l)                   + fabsf(cc - rr)
                + fabsf(cc - nl) + fabsf(cc - nc) + fabsf(cc - nr);
        o[j] = fmaf(a, s, cc);
    }
    float4* po = oi + (size_t)r * ROW_F4 + lane * 2;
    __stcs(po,     make_float4(o[0], o[1], o[2], o[3]));
    __stcs(po + 1, make_float4(o[4], o[5], o[6], o[7]));
}

__global__ void __launch_bounds__(BLOCK_THREADS)
adc_kernel(const float* __restrict__ x, const float* __restrict__ alpha,
           float* __restrict__ out) {
    __shared__ float4 tile[TILE_ROWS * PAD_F4];    // 35904 B

    int t     = threadIdx.x;
    int bx    = blockIdx.x;
    int img   = bx >> 3;                           // b*64 + c
    int strip = bx & 7;
    int ch    = img & 63;
    int r0    = strip * STRIP_ROWS;

    const float4* xi = reinterpret_cast<const float4*>(x) + (size_t)img * IMG_H * ROW_F4;
    float4*       oi = reinterpret_cast<float4*>(out)     + (size_t)img * IMG_H * ROW_F4;

    // ---- Phase 1: GMEM -> SMEM, 9 independent loads per thread ----
#pragma unroll
    for (int k = 0; k < 9; ++k) {
        int idx = t + k * BLOCK_THREADS;
        if (idx < TILE_F4) {
            int i  = idx >> 6;                     // smem row 0..33
            int c4 = idx & 63;
            int gr = r0 - 1 + i;                   // global row
            float4 v = make_float4(0.f, 0.f, 0.f, 0.f);
            if (gr >= 0 && gr < IMG_H)
                v = __ldcs(xi + (size_t)gr * ROW_F4 + c4);
            tile[i * PAD_F4 + c4] = v;
        }
    }

    float a = __ldg(&alpha[ch]);
    __syncthreads();

    // ---- Phase 2: warp w computes output rows r0+4w .. r0+4w+3 ----
    int w    = t >> 5;                             // 0..7
    int lane = t & 31;
    int base = w * ROWS_PER_WARP;                  // smem row of first prev-row

    Row p = load_srow(tile, base,     lane);
    Row c = load_srow(tile, base + 1, lane);

#pragma unroll
    for (int m = 0; m < ROWS_PER_WARP; ++m) {
        Row n = load_srow(tile, base + 2 + m, lane);
        compute_store(p, c, n, a, oi, r0 + base + m, lane);
        p = c;
        c = n;
    }
}

extern "C" void kernel_launch(void* const* d_in, const int* in_sizes, int n_in,
                              void* d_out, int out_size) {
    const float* x     = (const float*)d_in[0];
    const float* alpha = (const float*)d_in[1];
    float*       out   = (float*)d_out;
    adc_kernel<<<GRID_BLOCKS, BLOCK_THREADS>>>(x, alpha, out);
}

// round 14
// speedup vs baseline: 1.0799x; 1.0799x over previous
#include <cuda_runtime.h>

// ADC module: out = x + alpha_c * sum_{3x3, zero-pad} |x - neighbor|
// x: (8, 64, 256, 256) fp32, alpha: (64,) fp32
//
// R12: R3 baseline structure (one warp per 32-row strip, lane owns 8 cols,
// shfl lane-halos) + 4-slot row ring with prefetch distance 1.
// The x4-unrolled loop uses static slot indices so the compiler renames
// registers instead of emitting rotation MOVs (R5's failure mode).
// Per iteration: raw-load row r+m+2 -> shfl-finish row r+m+1 (issued last
// iteration, latency already covered) -> compute+store row r+m.
// Keeps ~1KB per warp in flight through the compute window.

#define IMG_H 256
#define IMG_W 256
#define STRIP_ROWS 32
#define N_IMG (8 * 64)
#define STRIPS_PER_IMG (IMG_H / STRIP_ROWS)   // 8
#define TOTAL_WARPS (N_IMG * STRIPS_PER_IMG)  // 4096
#define BLOCK_THREADS 128
#define GRID_BLOCKS (TOTAL_WARPS * 32 / BLOCK_THREADS)  // 1024

struct Row {
    float v[8];
    float lh, rh;
};

// Issue the two vector loads only — no dependent ops, keeps LDGs in flight.
__device__ __forceinline__ void load_raw(Row& row, const float* __restrict__ img,
                                         int r, int rlo, int rhi, int lane) {
    if (r >= rlo && r <= rhi) {
        const float4* p = reinterpret_cast<const float4*>(img + (size_t)r * IMG_W + lane * 8);
        float4 a = __ldcs(p);
        float4 b = __ldcs(p + 1);
        row.v[0] = a.x; row.v[1] = a.y; row.v[2] = a.z; row.v[3] = a.w;
        row.v[4] = b.x; row.v[5] = b.y; row.v[6] = b.z; row.v[7] = b.w;
    } else {
#pragma unroll
        for (int i = 0; i < 8; i++) row.v[i] = 0.0f;
    }
}

// Consume the loaded values (lane-halo exchange) — done one iteration later.
__device__ __forceinline__ void finish_row(Row& row, int lane) {
    float left  = __shfl_up_sync(0xffffffffu, row.v[7], 1);
    float right = __shfl_down_sync(0xffffffffu, row.v[0], 1);
    row.lh = (lane == 0)  ? 0.0f : left;
    row.rh = (lane == 31) ? 0.0f : right;
}

__device__ __forceinline__ void compute_store(const Row& p, const Row& c, const Row& n,
                                              float a, float* __restrict__ oi,
                                              int r, int lane) {
    float o[8];
#pragma unroll
    for (int j = 0; j < 8; ++j) {
        float cc = c.v[j];
        float pl = (j == 0) ? p.lh : p.v[j - 1];
        float pc = p.v[j];
        float pr = (j == 7) ? p.rh : p.v[j + 1];
        float l  = (j == 0) ? c.lh : c.v[j - 1];
        float rr = (j == 7) ? c.rh : c.v[j + 1];
        float nl = (j == 0) ? n.lh : n.v[j - 1];
        float nc = n.v[j];
        float nr = (j == 7) ? n.rh : n.v[j + 1];

        // center tap |c-c| == 0 for finite inputs -> skipped
        float s = fabsf(cc - pl) + fabsf(cc - pc) + fabsf(cc - pr)
                + fabsf(cc - l)                   + fabsf(cc - rr)
                + fabsf(cc - nl) + fabsf(cc - nc) + fabsf(cc - nr);
        o[j] = fmaf(a, s, cc);
    }
    float4* po = reinterpret_cast<float4*>(oi + (size_t)r * IMG_W + lane * 8);
    __stcs(po,     make_float4(o[0], o[1], o[2], o[3]));
    __stcs(po + 1, make_float4(o[4], o[5], o[6], o[7]));
}

__global__ void __launch_bounds__(BLOCK_THREADS)
adc_kernel(const float* __restrict__ x, const float* __restrict__ alpha,
           float* __restrict__ out) {
    int gwarp = (blockIdx.x * BLOCK_THREADS + threadIdx.x) >> 5;
    int lane  = threadIdx.x & 31;

    int img   = gwarp / STRIPS_PER_IMG;
    int strip = gwarp - img * STRIPS_PER_IMG;
    int ch    = img & 63;
    float a   = __ldg(&alpha[ch]);

    const float* xi = x   + (size_t)img * IMG_H * IMG_W;
    float*       oi = out + (size_t)img * IMG_H * IMG_W;

    int r0  = strip * STRIP_ROWS;
    // Rows actually needed: [r0-1, r0+STRIP_ROWS], clipped to the image.
    int rlo = (r0 - 1 < 0) ? 0 : r0 - 1;
    int rhi = (r0 + STRIP_ROWS > IMG_H - 1) ? IMG_H - 1 : r0 + STRIP_ROWS;

    // Ring: row k lives in slot (k - (r0-1)) & 3.
    Row ring[4];
    load_raw(ring[0], xi, r0 - 1, rlo, rhi, lane);
    load_raw(ring[1], xi, r0,     rlo, rhi, lane);
    load_raw(ring[2], xi, r0 + 1, rlo, rhi, lane);   // raw; finished in m=0
    finish_row(ring[0], lane);
    finish_row(ring[1], lane);

    for (int r = r0; r < r0 + STRIP_ROWS; r += 4) {
#pragma unroll
        for (int m = 0; m < 4; ++m) {
            // 1) prefetch row r+m+2 into the dead slot (held row r+m-2)
            load_raw(ring[(m + 3) & 3], xi, r + m + 2, rlo, rhi, lane);
            // 2) finish row r+m+1 (raw-loaded one iteration ago)
            finish_row(ring[(m + 2) & 3], lane);
            // 3) compute+store row r+m from finished rows
            compute_store(ring[m & 3], ring[(m + 1) & 3], ring[(m + 2) & 3],
                          a, oi, r + m, lane);
        }
    }
}

extern "C" void kernel_launch(void* const* d_in, const int* in_sizes, int n_in,
                              void* d_out, int out_size) {
    const float* x     = (const float*)d_in[0];
    const float* alpha = (const float*)d_in[1];
    float*       out   = (float*)d_out;
    adc_kernel<<<GRID_BLOCKS, BLOCK_THREADS>>>(x, alpha, out);
}